// round 1
// baseline (speedup 1.0000x reference)
#include <cuda_runtime.h>
#include <cstddef>

#define K_DIM 2048
#define M_DIM 512
#define N_DIM 64
#define TK    8
#define EPS_F 1e-8f

// ---------------------------------------------------------------------------
// Kernel A: per-column threshold (8th largest of w_b[:,n]) -> scores_hard
// One block, 64 threads, one thread per output column n.
// ---------------------------------------------------------------------------
__global__ void hard_kernel(const float* __restrict__ w_b,
                            float* __restrict__ hard) {
    int n = threadIdx.x;  // 0..63
    float t[8];
#pragma unroll
    for (int i = 0; i < 8; i++) t[i] = -3.402823466e38f;

    for (int m = 0; m < M_DIM; m++) {
        float v = w_b[m * N_DIM + n];
        if (v > t[7]) {
            t[7] = v;
#pragma unroll
            for (int i = 7; i > 0; i--) {
                if (t[i] > t[i - 1]) {
                    float tmp = t[i - 1];
                    t[i - 1] = t[i];
                    t[i] = tmp;
                }
            }
        }
    }
    float thr = t[7];

    for (int m = 0; m < M_DIM; m++) {
        float sh = w_b[m * N_DIM + n] - thr + EPS_F;
        sh = fminf(fmaxf(sh, -1.0f), 1.0f);
        hard[m * N_DIM + n] = (sh + 1.0f) * 0.5f;
    }
}

// ---------------------------------------------------------------------------
// Kernel B: fused GEMM (x @ w_att) + softmax(+EPS) + broadcast writes.
// Block = 512 threads handles TK=8 rows of x. Thread j owns column j of S.
// ---------------------------------------------------------------------------
__global__ __launch_bounds__(512, 2)
void fused_kernel(const float* __restrict__ x,
                  const float* __restrict__ w_att,
                  const float* __restrict__ hard,
                  float* __restrict__ out,
                  float* __restrict__ soft_out,
                  float* __restrict__ mask_out) {
    __shared__ __align__(16) float x_sh[TK][M_DIM];
    __shared__ __align__(16) float soft_sh[TK][M_DIM];
    __shared__ float red[17];

    const int tid  = threadIdx.x;
    const int lane = tid & 31;
    const int wid  = tid >> 5;
    const int k0   = blockIdx.x * TK;

    // ---- load 8 x-rows into shared ----
    for (int e = tid; e < TK * M_DIM; e += 512) {
        int r = e >> 9;
        int j = e & (M_DIM - 1);
        x_sh[r][j] = x[(size_t)(k0 + r) * M_DIM + j];
    }
    __syncthreads();

    // ---- GEMM: acc[r] = sum_i x_sh[r][i] * w_att[i][j] ----
    float acc[TK];
#pragma unroll
    for (int r = 0; r < TK; r++) acc[r] = 0.0f;

    const int j = tid;  // column owned by this thread
    for (int i = 0; i < M_DIM; i += 4) {
        float w0 = w_att[(size_t)(i + 0) * M_DIM + j];
        float w1 = w_att[(size_t)(i + 1) * M_DIM + j];
        float w2 = w_att[(size_t)(i + 2) * M_DIM + j];
        float w3 = w_att[(size_t)(i + 3) * M_DIM + j];
#pragma unroll
        for (int r = 0; r < TK; r++) {
            float4 xv = *(const float4*)&x_sh[r][i];
            acc[r] = fmaf(xv.x, w0, acc[r]);
            acc[r] = fmaf(xv.y, w1, acc[r]);
            acc[r] = fmaf(xv.z, w2, acc[r]);
            acc[r] = fmaf(xv.w, w3, acc[r]);
        }
    }

    // ---- softmax over the 512 columns (one value per thread), per row ----
#pragma unroll 1
    for (int r = 0; r < TK; r++) {
        // block max
        float v = acc[r];
#pragma unroll
        for (int o = 16; o; o >>= 1)
            v = fmaxf(v, __shfl_xor_sync(0xffffffffu, v, o));
        if (lane == 0) red[wid] = v;
        __syncthreads();
        if (tid < 32) {
            float w = (lane < 16) ? red[lane] : -3.402823466e38f;
#pragma unroll
            for (int o = 8; o; o >>= 1)
                w = fmaxf(w, __shfl_xor_sync(0xffffffffu, w, o));
            if (lane == 0) red[16] = w;
        }
        __syncthreads();
        float rowmax = red[16];

        float e = __expf(acc[r] - rowmax);

        // block sum
        v = e;
#pragma unroll
        for (int o = 16; o; o >>= 1)
            v += __shfl_xor_sync(0xffffffffu, v, o);
        if (lane == 0) red[wid] = v;
        __syncthreads();
        if (tid < 32) {
            float w = (lane < 16) ? red[lane] : 0.0f;
#pragma unroll
            for (int o = 8; o; o >>= 1)
                w += __shfl_xor_sync(0xffffffffu, w, o);
            if (lane == 0) red[16] = w;
        }
        __syncthreads();
        float s = e / red[16] + EPS_F;

        soft_sh[r][j] = s;
        soft_out[(size_t)(k0 + r) * M_DIM + j] = s;
        __syncthreads();  // protect red[] for next r
    }

    // ---- broadcast writes: mask = hard*soft, out = mask*x ----
    // float4 over n: TK * M * (N/4) = 65536 float4 per array per block,
    // linear index e maps exactly to the block's contiguous output region.
    const float4* hard4 = (const float4*)hard;
    float4* out4  = (float4*)out      + (size_t)k0 * M_DIM * (N_DIM / 4);
    float4* mask4 = (float4*)mask_out + (size_t)k0 * M_DIM * (N_DIM / 4);

    for (int e = tid; e < TK * M_DIM * (N_DIM / 4); e += 512) {
        int n4 = e & 15;
        int m  = (e >> 4) & (M_DIM - 1);
        int r  = e >> 13;

        float4 h = hard4[m * (N_DIM / 4) + n4];
        float  s = soft_sh[r][m];
        float xv = x_sh[r][m];

        float4 mw, o;
        mw.x = h.x * s;  mw.y = h.y * s;  mw.z = h.z * s;  mw.w = h.w * s;
        o.x = mw.x * xv; o.y = mw.y * xv; o.z = mw.z * xv; o.w = mw.w * xv;

        mask4[e] = mw;
        out4[e]  = o;
    }
}

// ---------------------------------------------------------------------------
// d_out layout (reference return order):
//   out         [K,M,N] : offset 0           (67,108,864)
//   scores_hard [M,N]   : offset 67,108,864  (32,768)
//   scores_soft [K,M]   : offset 67,141,632  (1,048,576)
//   mask_weight [K,M,N] : offset 68,190,208  (67,108,864)
// ---------------------------------------------------------------------------
extern "C" void kernel_launch(void* const* d_in, const int* in_sizes, int n_in,
                              void* d_out, int out_size) {
    const float* x     = (const float*)d_in[0];
    const float* w_att = (const float*)d_in[1];
    const float* w_b   = (const float*)d_in[2];

    float* out  = (float*)d_out;
    float* hard = out + 67108864ULL;
    float* soft = out + 67141632ULL;
    float* mask = out + 68190208ULL;

    hard_kernel<<<1, 64>>>(w_b, hard);
    fused_kernel<<<K_DIM / TK, 512>>>(x, w_att, hard, out, soft, mask);
}

// round 2
// speedup vs baseline: 1.4961x; 1.4961x over previous
#include <cuda_runtime.h>
#include <cstddef>

#define K_DIM 2048
#define M_DIM 512
#define N_DIM 64
#define TK    8
#define EPS_F 1e-8f

// ---------------------------------------------------------------------------
// Kernel A: per-column threshold (8th largest of w_b[:,n]) -> scores_hard.
// 64 blocks (one per column n) x 512 threads (one per m).
// Exact selection via rank counting with tie handling:
//   thr is the value v with count_greater(v) <= 7 and
//   count_greater(v)+count_equal(v) >= 8  (== 8th largest incl. duplicates)
// ---------------------------------------------------------------------------
__global__ __launch_bounds__(512)
void hard_kernel(const float* __restrict__ w_b,
                 float* __restrict__ hard) {
    __shared__ float col[M_DIM];
    __shared__ float thr_sh;

    const int n = blockIdx.x;   // column
    const int t = threadIdx.x;  // row m

    col[t] = w_b[t * N_DIM + n];
    __syncthreads();

    const float v = col[t];
    int cg = 0, ce = 0;
#pragma unroll 8
    for (int i = 0; i < M_DIM; i++) {
        float u = col[i];
        cg += (u > v);
        ce += (u == v);
    }
    if (cg <= 7 && cg + ce >= 8) thr_sh = v;
    __syncthreads();

    float sh = col[t] - thr_sh + EPS_F;
    sh = fminf(fmaxf(sh, -1.0f), 1.0f);
    hard[t * N_DIM + n] = (sh + 1.0f) * 0.5f;
}

// ---------------------------------------------------------------------------
// Kernel B: GEMM (x @ w_att) + softmax(+EPS) -> soft [K, M].
// Block = 512 threads handles TK=8 rows of x; thread j owns column j of S.
// x_sh reads are warp-broadcast LDS (conflict-free); w_att reads coalesced.
// ---------------------------------------------------------------------------
__global__ __launch_bounds__(512, 2)
void gemm_softmax_kernel(const float* __restrict__ x,
                         const float* __restrict__ w_att,
                         float* __restrict__ soft_out) {
    __shared__ __align__(16) float x_sh[TK][M_DIM];
    __shared__ float red[17];

    const int tid  = threadIdx.x;
    const int lane = tid & 31;
    const int wid  = tid >> 5;
    const int k0   = blockIdx.x * TK;

    for (int e = tid; e < TK * M_DIM; e += 512) {
        int r = e >> 9;
        int j = e & (M_DIM - 1);
        x_sh[r][j] = x[(size_t)(k0 + r) * M_DIM + j];
    }
    __syncthreads();

    float acc[TK];
#pragma unroll
    for (int r = 0; r < TK; r++) acc[r] = 0.0f;

    const int j = tid;
    for (int i = 0; i < M_DIM; i += 4) {
        float w0 = w_att[(size_t)(i + 0) * M_DIM + j];
        float w1 = w_att[(size_t)(i + 1) * M_DIM + j];
        float w2 = w_att[(size_t)(i + 2) * M_DIM + j];
        float w3 = w_att[(size_t)(i + 3) * M_DIM + j];
#pragma unroll
        for (int r = 0; r < TK; r++) {
            float4 xv = *(const float4*)&x_sh[r][i];
            acc[r] = fmaf(xv.x, w0, acc[r]);
            acc[r] = fmaf(xv.y, w1, acc[r]);
            acc[r] = fmaf(xv.z, w2, acc[r]);
            acc[r] = fmaf(xv.w, w3, acc[r]);
        }
    }

#pragma unroll 1
    for (int r = 0; r < TK; r++) {
        // block max
        float v = acc[r];
#pragma unroll
        for (int o = 16; o; o >>= 1)
            v = fmaxf(v, __shfl_xor_sync(0xffffffffu, v, o));
        if (lane == 0) red[wid] = v;
        __syncthreads();
        if (tid < 32) {
            float w = (lane < 16) ? red[lane] : -3.402823466e38f;
#pragma unroll
            for (int o = 8; o; o >>= 1)
                w = fmaxf(w, __shfl_xor_sync(0xffffffffu, w, o));
            if (lane == 0) red[16] = w;
        }
        __syncthreads();
        float rowmax = red[16];

        float e = __expf(acc[r] - rowmax);

        // block sum
        v = e;
#pragma unroll
        for (int o = 16; o; o >>= 1)
            v += __shfl_xor_sync(0xffffffffu, v, o);
        if (lane == 0) red[wid] = v;
        __syncthreads();
        if (tid < 32) {
            float w = (lane < 16) ? red[lane] : 0.0f;
#pragma unroll
            for (int o = 8; o; o >>= 1)
                w += __shfl_xor_sync(0xffffffffu, w, o);
            if (lane == 0) red[16] = w;
        }
        __syncthreads();

        soft_out[(size_t)(k0 + r) * M_DIM + j] = e / red[16] + EPS_F;
        __syncthreads();  // protect red[] for next r
    }
}

// ---------------------------------------------------------------------------
// Kernel C: broadcast streaming writes.
//   mask[k,m,n] = hard[m,n] * soft[k,m]
//   out [k,m,n] = mask[k,m,n] * x[k,m]
// One block per k. hard (128 KB) stays L1-resident; soft/x rows in shared.
// 2 x STG.128 per thread-iteration, fully coalesced & contiguous.
// ---------------------------------------------------------------------------
__global__ __launch_bounds__(256)
void bcast_kernel(const float* __restrict__ x,
                  const float* __restrict__ soft,
                  const float* __restrict__ hard,
                  float* __restrict__ out,
                  float* __restrict__ mask) {
    __shared__ float s_sh[M_DIM];
    __shared__ float p_sh[M_DIM];

    const int k = blockIdx.x;

    for (int m = threadIdx.x; m < M_DIM; m += 256) {
        float s  = soft[(size_t)k * M_DIM + m];
        float xv = x[(size_t)k * M_DIM + m];
        s_sh[m] = s;
        p_sh[m] = s * xv;
    }
    __syncthreads();

    const float4* h4 = (const float4*)hard;                       // 8192 entries
    float4* o4 = (float4*)out  + (size_t)k * (M_DIM * N_DIM / 4); // 8192 / k
    float4* m4 = (float4*)mask + (size_t)k * (M_DIM * N_DIM / 4);

#pragma unroll 4
    for (int e = threadIdx.x; e < M_DIM * N_DIM / 4; e += 256) {
        int m = e >> 4;
        float4 h = h4[e];
        float s = s_sh[m];
        float p = p_sh[m];

        float4 mw, o;
        mw.x = h.x * s; mw.y = h.y * s; mw.z = h.z * s; mw.w = h.w * s;
        o.x  = h.x * p; o.y  = h.y * p; o.z  = h.z * p; o.w  = h.w * p;

        m4[e] = mw;
        o4[e] = o;
    }
}

// ---------------------------------------------------------------------------
// d_out layout (reference return order):
//   out         [K,M,N] : offset 0           (67,108,864)
//   scores_hard [M,N]   : offset 67,108,864  (32,768)
//   scores_soft [K,M]   : offset 67,141,632  (1,048,576)
//   mask_weight [K,M,N] : offset 68,190,208  (67,108,864)
// ---------------------------------------------------------------------------
extern "C" void kernel_launch(void* const* d_in, const int* in_sizes, int n_in,
                              void* d_out, int out_size) {
    const float* x     = (const float*)d_in[0];
    const float* w_att = (const float*)d_in[1];
    const float* w_b   = (const float*)d_in[2];

    float* out  = (float*)d_out;
    float* hard = out + 67108864ULL;
    float* soft = out + 67141632ULL;
    float* mask = out + 68190208ULL;

    hard_kernel<<<N_DIM, 512>>>(w_b, hard);
    gemm_softmax_kernel<<<K_DIM / TK, 512>>>(x, w_att, soft);
    bcast_kernel<<<K_DIM, 256>>>(x, soft, hard, out, mask);
}

// round 3
// speedup vs baseline: 1.7556x; 1.1735x over previous
#include <cuda_runtime.h>
#include <cstddef>

#define K_DIM 2048
#define M_DIM 512
#define N_DIM 64
#define TK    8
#define EPS_F 1e-8f
#define GEMM_BLOCKS (K_DIM / TK)   // 256
#define HARD_BLOCKS 4              // 16 warps/block, warp-per-column, 64 cols

// ---------------------------------------------------------------------------
// Combined kernel: blocks [0,256) do GEMM(x@w_att)+softmax -> soft [K,M].
// Blocks [256,260) compute scores_hard from w_b (warp per column, exact
// multiset 8th-largest via per-lane top-8 + 8 warp-max extractions).
// One wave (260 blocks, occ 2/SM on 148 SMs) -> hard cost fully hidden.
// ---------------------------------------------------------------------------
__global__ __launch_bounds__(512, 2)
void gemm_softmax_hard_kernel(const float* __restrict__ x,
                              const float* __restrict__ w_att,
                              const float* __restrict__ w_b,
                              float* __restrict__ soft_out,
                              float* __restrict__ hard_out) {
    const int tid  = threadIdx.x;
    const int lane = tid & 31;
    const int wid  = tid >> 5;

    if (blockIdx.x >= GEMM_BLOCKS) {
        // ---------------- hard path: warp per column n ----------------
        const int n = (blockIdx.x - GEMM_BLOCKS) * 16 + wid;  // 0..63

        // per-lane values: rows lane, lane+32, ..., lane+480
        float v[16];
#pragma unroll
        for (int j = 0; j < 16; j++)
            v[j] = w_b[(lane + 32 * j) * N_DIM + n];

        // per-lane top-8 (descending insertion)
        float t[8];
#pragma unroll
        for (int i = 0; i < 8; i++) t[i] = -3.402823466e38f;
#pragma unroll
        for (int j = 0; j < 16; j++) {
            float val = v[j];
            if (val > t[7]) {
                t[7] = val;
#pragma unroll
                for (int i = 7; i > 0; i--) {
                    if (t[i] > t[i - 1]) {
                        float tmp = t[i - 1]; t[i - 1] = t[i]; t[i] = tmp;
                    }
                }
            }
        }

        // 8 warp-wide max extractions; 8th extracted value = threshold
        float thr = 0.0f;
#pragma unroll
        for (int it = 0; it < 8; it++) {
            float m = t[0];
#pragma unroll
            for (int o = 16; o; o >>= 1)
                m = fmaxf(m, __shfl_xor_sync(0xffffffffu, m, o));
            unsigned bal = __ballot_sync(0xffffffffu, t[0] == m);
            int src = __ffs(bal) - 1;
            if (lane == src) {
#pragma unroll
                for (int i = 0; i < 7; i++) t[i] = t[i + 1];
                t[7] = -3.402823466e38f;
            }
            thr = m;
        }

        // write scores_hard for this column
#pragma unroll
        for (int j = 0; j < 16; j++) {
            float sh = v[j] - thr + EPS_F;
            sh = fminf(fmaxf(sh, -1.0f), 1.0f);
            hard_out[(lane + 32 * j) * N_DIM + n] = (sh + 1.0f) * 0.5f;
        }
        return;
    }

    // ---------------- gemm + softmax path ----------------
    __shared__ __align__(16) float x_sh[TK][M_DIM];
    __shared__ float red[17];

    const int k0 = blockIdx.x * TK;

    for (int e = tid; e < TK * M_DIM; e += 512) {
        int r = e >> 9;
        int j = e & (M_DIM - 1);
        x_sh[r][j] = x[(size_t)(k0 + r) * M_DIM + j];
    }
    __syncthreads();

    float acc[TK];
#pragma unroll
    for (int r = 0; r < TK; r++) acc[r] = 0.0f;

    const int j = tid;
    for (int i = 0; i < M_DIM; i += 4) {
        float w0 = w_att[(size_t)(i + 0) * M_DIM + j];
        float w1 = w_att[(size_t)(i + 1) * M_DIM + j];
        float w2 = w_att[(size_t)(i + 2) * M_DIM + j];
        float w3 = w_att[(size_t)(i + 3) * M_DIM + j];
#pragma unroll
        for (int r = 0; r < TK; r++) {
            float4 xv = *(const float4*)&x_sh[r][i];
            acc[r] = fmaf(xv.x, w0, acc[r]);
            acc[r] = fmaf(xv.y, w1, acc[r]);
            acc[r] = fmaf(xv.z, w2, acc[r]);
            acc[r] = fmaf(xv.w, w3, acc[r]);
        }
    }

#pragma unroll 1
    for (int r = 0; r < TK; r++) {
        float v = acc[r];
#pragma unroll
        for (int o = 16; o; o >>= 1)
            v = fmaxf(v, __shfl_xor_sync(0xffffffffu, v, o));
        if (lane == 0) red[wid] = v;
        __syncthreads();
        if (tid < 32) {
            float w = (lane < 16) ? red[lane] : -3.402823466e38f;
#pragma unroll
            for (int o = 8; o; o >>= 1)
                w = fmaxf(w, __shfl_xor_sync(0xffffffffu, w, o));
            if (lane == 0) red[16] = w;
        }
        __syncthreads();
        float rowmax = red[16];

        float e = __expf(acc[r] - rowmax);

        v = e;
#pragma unroll
        for (int o = 16; o; o >>= 1)
            v += __shfl_xor_sync(0xffffffffu, v, o);
        if (lane == 0) red[wid] = v;
        __syncthreads();
        if (tid < 32) {
            float w = (lane < 16) ? red[lane] : 0.0f;
#pragma unroll
            for (int o = 8; o; o >>= 1)
                w += __shfl_xor_sync(0xffffffffu, w, o);
            if (lane == 0) red[16] = w;
        }
        __syncthreads();

        soft_out[(size_t)(k0 + r) * M_DIM + j] = e / red[16] + EPS_F;
        __syncthreads();
    }
}

// ---------------------------------------------------------------------------
// bcast: mask[k,m,n] = hard[m,n]*soft[k,m];  out[k,m,n] = mask*x[k,m].
// One block per k, 512 threads, __stcs streaming stores (never re-read).
// hard (128 KB) is L1-resident across a SM's block sequence.
// ---------------------------------------------------------------------------
__global__ __launch_bounds__(512)
void bcast_kernel(const float* __restrict__ x,
                  const float* __restrict__ soft,
                  const float* __restrict__ hard,
                  float* __restrict__ out,
                  float* __restrict__ mask) {
    __shared__ float s_sh[M_DIM];
    __shared__ float p_sh[M_DIM];

    const int k = blockIdx.x;
    {
        int m = threadIdx.x;  // 512 threads, one per m
        float s  = soft[(size_t)k * M_DIM + m];
        float xv = x[(size_t)k * M_DIM + m];
        s_sh[m] = s;
        p_sh[m] = s * xv;
    }
    __syncthreads();

    const float4* h4 = (const float4*)hard;                       // 8192 entries
    float4* o4 = (float4*)out  + (size_t)k * (M_DIM * N_DIM / 4);
    float4* m4 = (float4*)mask + (size_t)k * (M_DIM * N_DIM / 4);

#pragma unroll 4
    for (int e = threadIdx.x; e < M_DIM * N_DIM / 4; e += 512) {
        int m = e >> 4;
        float4 h = h4[e];
        float s = s_sh[m];
        float p = p_sh[m];

        float4 mw, o;
        mw.x = h.x * s; mw.y = h.y * s; mw.z = h.z * s; mw.w = h.w * s;
        o.x  = h.x * p; o.y  = h.y * p; o.z  = h.z * p; o.w  = h.w * p;

        __stcs(&m4[e], mw);
        __stcs(&o4[e], o);
    }
}

// ---------------------------------------------------------------------------
// d_out layout (reference return order):
//   out         [K,M,N] : offset 0           (67,108,864)
//   scores_hard [M,N]   : offset 67,108,864  (32,768)
//   scores_soft [K,M]   : offset 67,141,632  (1,048,576)
//   mask_weight [K,M,N] : offset 68,190,208  (67,108,864)
// ---------------------------------------------------------------------------
extern "C" void kernel_launch(void* const* d_in, const int* in_sizes, int n_in,
                              void* d_out, int out_size) {
    const float* x     = (const float*)d_in[0];
    const float* w_att = (const float*)d_in[1];
    const float* w_b   = (const float*)d_in[2];

    float* out  = (float*)d_out;
    float* hard = out + 67108864ULL;
    float* soft = out + 67141632ULL;
    float* mask = out + 68190208ULL;

    gemm_softmax_hard_kernel<<<GEMM_BLOCKS + HARD_BLOCKS, 512>>>(
        x, w_att, w_b, soft, hard);
    bcast_kernel<<<K_DIM, 512>>>(x, soft, hard, out, mask);
}

// round 4
// speedup vs baseline: 1.7861x; 1.0174x over previous
#include <cuda_runtime.h>
#include <cstddef>

#define K_DIM 2048
#define M_DIM 512
#define N_DIM 64
#define TK    8
#define EPS_F 1e-8f
#define GEMM_BLOCKS (K_DIM / TK)   // 256
#define HARD_BLOCKS 4              // 16 warps/block, warp-per-column, 64 cols

// ---------------------------------------------------------------------------
// Combined kernel: blocks [0,256) do GEMM(x@w_att)+softmax -> soft [K,M]
// using packed fp32x2 FMA (FFMA2) with even/odd-i lane split.
// Blocks [256,260) compute scores_hard from w_b (warp per column, exact
// multiset 8th-largest). One wave -> hard fully hidden.
// ---------------------------------------------------------------------------
__global__ __launch_bounds__(512, 2)
void gemm_softmax_hard_kernel(const float* __restrict__ x,
                              const float* __restrict__ w_att,
                              const float* __restrict__ w_b,
                              float* __restrict__ soft_out,
                              float* __restrict__ hard_out) {
    const int tid  = threadIdx.x;
    const int lane = tid & 31;
    const int wid  = tid >> 5;

    if (blockIdx.x >= GEMM_BLOCKS) {
        // ---------------- hard path: warp per column n ----------------
        const int n = (blockIdx.x - GEMM_BLOCKS) * 16 + wid;  // 0..63

        float v[16];
#pragma unroll
        for (int j = 0; j < 16; j++)
            v[j] = w_b[(lane + 32 * j) * N_DIM + n];

        float t[8];
#pragma unroll
        for (int i = 0; i < 8; i++) t[i] = -3.402823466e38f;
#pragma unroll
        for (int j = 0; j < 16; j++) {
            float val = v[j];
            if (val > t[7]) {
                t[7] = val;
#pragma unroll
                for (int i = 7; i > 0; i--) {
                    if (t[i] > t[i - 1]) {
                        float tmp = t[i - 1]; t[i - 1] = t[i]; t[i] = tmp;
                    }
                }
            }
        }

        float thr = 0.0f;
#pragma unroll
        for (int it = 0; it < 8; it++) {
            float m = t[0];
#pragma unroll
            for (int o = 16; o; o >>= 1)
                m = fmaxf(m, __shfl_xor_sync(0xffffffffu, m, o));
            unsigned bal = __ballot_sync(0xffffffffu, t[0] == m);
            int src = __ffs(bal) - 1;
            if (lane == src) {
#pragma unroll
                for (int i = 0; i < 7; i++) t[i] = t[i + 1];
                t[7] = -3.402823466e38f;
            }
            thr = m;
        }

#pragma unroll
        for (int j = 0; j < 16; j++) {
            float sh = v[j] - thr + EPS_F;
            sh = fminf(fmaxf(sh, -1.0f), 1.0f);
            hard_out[(lane + 32 * j) * N_DIM + n] = (sh + 1.0f) * 0.5f;
        }
        return;
    }

    // ---------------- gemm + softmax path ----------------
    __shared__ __align__(16) float x_sh[TK][M_DIM];
    __shared__ float red[17];

    const int k0 = blockIdx.x * TK;

    for (int e = tid; e < TK * M_DIM; e += 512) {
        int r = e >> 9;
        int j = e & (M_DIM - 1);
        x_sh[r][j] = x[(size_t)(k0 + r) * M_DIM + j];
    }
    __syncthreads();

    // acc2[r]: packed fp32x2, lane0 = even-i partial sum, lane1 = odd-i.
    unsigned long long acc2[TK];
#pragma unroll
    for (int r = 0; r < TK; r++) acc2[r] = 0ULL;

    const int j = tid;
    for (int i = 0; i < M_DIM; i += 4) {
        float w0 = w_att[(size_t)(i + 0) * M_DIM + j];
        float w1 = w_att[(size_t)(i + 1) * M_DIM + j];
        float w2 = w_att[(size_t)(i + 2) * M_DIM + j];
        float w3 = w_att[(size_t)(i + 3) * M_DIM + j];
        unsigned long long wp0, wp1;
        asm("mov.b64 %0, {%1, %2};" : "=l"(wp0) : "f"(w0), "f"(w1));
        asm("mov.b64 %0, {%1, %2};" : "=l"(wp1) : "f"(w2), "f"(w3));
#pragma unroll
        for (int r = 0; r < TK; r++) {
            // LDS.128 broadcast: (x[i],x[i+1]) and (x[i+2],x[i+3]) packed.
            ulonglong2 xp = *(const ulonglong2*)&x_sh[r][i];
            asm("fma.rn.f32x2 %0, %1, %2, %0;"
                : "+l"(acc2[r]) : "l"(xp.x), "l"(wp0));
            asm("fma.rn.f32x2 %0, %1, %2, %0;"
                : "+l"(acc2[r]) : "l"(xp.y), "l"(wp1));
        }
    }

    float acc[TK];
#pragma unroll
    for (int r = 0; r < TK; r++) {
        float lo, hi;
        asm("mov.b64 {%0, %1}, %2;" : "=f"(lo), "=f"(hi) : "l"(acc2[r]));
        acc[r] = lo + hi;
    }

#pragma unroll 1
    for (int r = 0; r < TK; r++) {
        float v = acc[r];
#pragma unroll
        for (int o = 16; o; o >>= 1)
            v = fmaxf(v, __shfl_xor_sync(0xffffffffu, v, o));
        if (lane == 0) red[wid] = v;
        __syncthreads();
        if (tid < 32) {
            float w = (lane < 16) ? red[lane] : -3.402823466e38f;
#pragma unroll
            for (int o = 8; o; o >>= 1)
                w = fmaxf(w, __shfl_xor_sync(0xffffffffu, w, o));
            if (lane == 0) red[16] = w;
        }
        __syncthreads();
        float rowmax = red[16];

        float e = __expf(acc[r] - rowmax);

        v = e;
#pragma unroll
        for (int o = 16; o; o >>= 1)
            v += __shfl_xor_sync(0xffffffffu, v, o);
        if (lane == 0) red[wid] = v;
        __syncthreads();
        if (tid < 32) {
            float w = (lane < 16) ? red[lane] : 0.0f;
#pragma unroll
            for (int o = 8; o; o >>= 1)
                w += __shfl_xor_sync(0xffffffffu, w, o);
            if (lane == 0) red[16] = w;
        }
        __syncthreads();

        soft_out[(size_t)(k0 + r) * M_DIM + j] = e / red[16] + EPS_F;
        __syncthreads();
    }
}

// ---------------------------------------------------------------------------
// bcast: mask[k,m,n] = hard[m,n]*soft[k,m];  out[k,m,n] = mask*x[k,m].
// One block per k, 512 threads, __stcs streaming stores.
// ---------------------------------------------------------------------------
__global__ __launch_bounds__(512)
void bcast_kernel(const float* __restrict__ x,
                  const float* __restrict__ soft,
                  const float* __restrict__ hard,
                  float* __restrict__ out,
                  float* __restrict__ mask) {
    __shared__ float s_sh[M_DIM];
    __shared__ float p_sh[M_DIM];

    const int k = blockIdx.x;
    {
        int m = threadIdx.x;
        float s  = soft[(size_t)k * M_DIM + m];
        float xv = x[(size_t)k * M_DIM + m];
        s_sh[m] = s;
        p_sh[m] = s * xv;
    }
    __syncthreads();

    const float4* h4 = (const float4*)hard;
    float4* o4 = (float4*)out  + (size_t)k * (M_DIM * N_DIM / 4);
    float4* m4 = (float4*)mask + (size_t)k * (M_DIM * N_DIM / 4);

#pragma unroll 8
    for (int e = threadIdx.x; e < M_DIM * N_DIM / 4; e += 512) {
        int m = e >> 4;
        float4 h = h4[e];
        float s = s_sh[m];
        float p = p_sh[m];

        float4 mw, o;
        mw.x = h.x * s; mw.y = h.y * s; mw.z = h.z * s; mw.w = h.w * s;
        o.x  = h.x * p; o.y  = h.y * p; o.z  = h.z * p; o.w  = h.w * p;

        __stcs(&m4[e], mw);
        __stcs(&o4[e], o);
    }
}

// ---------------------------------------------------------------------------
// d_out layout (reference return order):
//   out         [K,M,N] : offset 0           (67,108,864)
//   scores_hard [M,N]   : offset 67,108,864  (32,768)
//   scores_soft [K,M]   : offset 67,141,632  (1,048,576)
//   mask_weight [K,M,N] : offset 68,190,208  (67,108,864)
// ---------------------------------------------------------------------------
extern "C" void kernel_launch(void* const* d_in, const int* in_sizes, int n_in,
                              void* d_out, int out_size) {
    const float* x     = (const float*)d_in[0];
    const float* w_att = (const float*)d_in[1];
    const float* w_b   = (const float*)d_in[2];

    float* out  = (float*)d_out;
    float* hard = out + 67108864ULL;
    float* soft = out + 67141632ULL;
    float* mask = out + 68190208ULL;

    gemm_softmax_hard_kernel<<<GEMM_BLOCKS + HARD_BLOCKS, 512>>>(
        x, w_att, w_b, soft, hard);
    bcast_kernel<<<K_DIM, 512>>>(x, soft, hard, out, mask);
}